// round 5
// baseline (speedup 1.0000x reference)
#include <cuda_runtime.h>
#include <cuda_bf16.h>
#include <math_constants.h>
#include <stdint.h>

#define B_   8
#define T_   4
#define De_  128
#define Do_  512
#define HW_  1024
#define THW_ 4096

#define SCALE_ 0.08838834764831843f   // 1/sqrt(128)

// ---------------------------------------------------------------------------
// Static scratch: bf16 split (hi/lo) operands, K-major layouts.
// ---------------------------------------------------------------------------
__device__ __align__(256) __nv_bfloat16 g_miT_hi[(size_t)32 * 1024 * 128];  // [bt][m][k]
__device__ __align__(256) __nv_bfloat16 g_miT_lo[(size_t)32 * 1024 * 128];
__device__ __align__(256) __nv_bfloat16 g_qiT_hi[(size_t)8 * 1024 * 128];   // [b][n][k] pre-scaled
__device__ __align__(256) __nv_bfloat16 g_qiT_lo[(size_t)8 * 1024 * 128];
__device__ __align__(256) __nv_bfloat16 g_mo_hi[(size_t)8 * 512 * 4096];    // [b][d][k]
__device__ __align__(256) __nv_bfloat16 g_mo_lo[(size_t)8 * 512 * 4096];
__device__ __align__(256) __nv_bfloat16 g_pT_hi[(size_t)8 * 1024 * 4096];   // [b][n][k]
__device__ __align__(256) __nv_bfloat16 g_pT_lo[(size_t)8 * 1024 * 4096];

// ---------------------------------------------------------------------------
// Conversion kernels
// ---------------------------------------------------------------------------
__global__ __launch_bounds__(256) void conv_mo_kernel(const float4* __restrict__ src) {
    const size_t i = (size_t)blockIdx.x * 256 + threadIdx.x;
    if (i >= (size_t)B_ * Do_ * THW_ / 4) return;
    const float4 v = src[i];
    const __nv_bfloat16 h0 = __float2bfloat16(v.x);
    const __nv_bfloat16 h1 = __float2bfloat16(v.y);
    const __nv_bfloat16 h2 = __float2bfloat16(v.z);
    const __nv_bfloat16 h3 = __float2bfloat16(v.w);
    ((__nv_bfloat162*)g_mo_hi)[i * 2 + 0] = __halves2bfloat162(h0, h1);
    ((__nv_bfloat162*)g_mo_hi)[i * 2 + 1] = __halves2bfloat162(h2, h3);
    const __nv_bfloat16 l0 = __float2bfloat16(v.x - __bfloat162float(h0));
    const __nv_bfloat16 l1 = __float2bfloat16(v.y - __bfloat162float(h1));
    const __nv_bfloat16 l2 = __float2bfloat16(v.z - __bfloat162float(h2));
    const __nv_bfloat16 l3 = __float2bfloat16(v.w - __bfloat162float(h3));
    ((__nv_bfloat162*)g_mo_lo)[i * 2 + 0] = __halves2bfloat162(l0, l1);
    ((__nv_bfloat162*)g_mo_lo)[i * 2 + 1] = __halves2bfloat162(l2, l3);
}

// Transpose + split-convert: src [z][R][C] fp32 -> dst [z][C][R] bf16 hi/lo
// which: 0 = miT, 1 = qiT
__global__ __launch_bounds__(256) void tconv_kernel(const float* __restrict__ src,
                                                    int R, int C, float scale, int which) {
    __shared__ float tile[32][33];
    __nv_bfloat16 *dhi, *dlo;
    if (which == 0) { dhi = g_miT_hi; dlo = g_miT_lo; }
    else            { dhi = g_qiT_hi; dlo = g_qiT_lo; }

    const size_t bo = (size_t)blockIdx.z * R * C;
    const int r0 = blockIdx.y * 32, c0 = blockIdx.x * 32;
    const int x = threadIdx.x, y = threadIdx.y;   // 32 x 8

    #pragma unroll
    for (int i = 0; i < 4; ++i)
        tile[y + 8 * i][x] = src[bo + (size_t)(r0 + y + 8 * i) * C + c0 + x];
    __syncthreads();

    #pragma unroll
    for (int i = 0; i < 4; ++i) {
        const float v = tile[x][y + 8 * i] * scale;
        const __nv_bfloat16 h = __float2bfloat16(v);
        const size_t o = bo + (size_t)(c0 + y + 8 * i) * R + r0 + x;
        dhi[o] = h;
        dlo[o] = __float2bfloat16(v - __bfloat162float(h));
    }
}

// ---------------------------------------------------------------------------
// Split-bf16 GEMM via mma.sync m16n8k16 + ldmatrix + cp.async double-buffer.
// CTA tile 128x128, KC=32, 8 warps (2m x 4n), warp tile 64x32.
// ---------------------------------------------------------------------------
#define KC       32
#define ROWB     80                      // smem row stride bytes (40 elems)
#define TILE_SB  (128 * ROWB)            // 10240 B per tile
#define BUF_SB   (4 * TILE_SB)           // A_hi A_lo B_hi B_lo
#define GSMEM    (2 * BUF_SB)            // 81920 B

static __device__ __forceinline__ void mma16816(float* c, const uint32_t* a,
                                                uint32_t b0, uint32_t b1) {
    asm volatile(
        "mma.sync.aligned.m16n8k16.row.col.f32.bf16.bf16.f32 "
        "{%0,%1,%2,%3}, {%4,%5,%6,%7}, {%8,%9}, {%0,%1,%2,%3};"
        : "+f"(c[0]), "+f"(c[1]), "+f"(c[2]), "+f"(c[3])
        : "r"(a[0]), "r"(a[1]), "r"(a[2]), "r"(a[3]), "r"(b0), "r"(b1));
}
static __device__ __forceinline__ void ldmx4(uint32_t* r, uint32_t addr) {
    asm volatile("ldmatrix.sync.aligned.m8n8.x4.shared.b16 {%0,%1,%2,%3}, [%4];"
                 : "=r"(r[0]), "=r"(r[1]), "=r"(r[2]), "=r"(r[3]) : "r"(addr));
}
static __device__ __forceinline__ void cpa16(uint32_t dst, const void* src) {
    asm volatile("cp.async.cg.shared.global [%0], [%1], 16;" :: "r"(dst), "l"(src));
}
static __device__ __forceinline__ void cpa_commit() {
    asm volatile("cp.async.commit_group;" ::: "memory");
}
template <int N> static __device__ __forceinline__ void cpa_wait() {
    asm volatile("cp.async.wait_group %0;" :: "n"(N) : "memory");
}

__global__ __launch_bounds__(256, 2) void gemm_bf16s(
    float* __restrict__ cbase, int K, int ldc,
    unsigned long long strideA, unsigned long long strideB,
    unsigned long long strideC, int bshift, int which)
{
    extern __shared__ __align__(16) char smem[];
    const uint32_t sb = (uint32_t)__cvta_generic_to_shared(smem);

    const int tid  = threadIdx.x;
    const int wid  = tid >> 5, lane = tid & 31;
    const int gid  = lane >> 2, tig = lane & 3;
    const int wm0  = (wid & 1) * 64;
    const int wn0  = (wid >> 1) * 32;
    const int z    = blockIdx.z;
    const int m0   = blockIdx.x * 128;
    const int n0   = blockIdx.y * 128;

    const __nv_bfloat16 *ahi, *alo, *bhi, *blo;
    if (which == 0) { ahi = g_miT_hi; alo = g_miT_lo; bhi = g_qiT_hi; blo = g_qiT_lo; }
    else            { ahi = g_mo_hi;  alo = g_mo_lo;  bhi = g_pT_hi;  blo = g_pT_lo;  }

    // cp.async loader mapping: thread t -> rows (t>>2, t>>2+64), 16B col chunk (t&3)
    const int lrow = tid >> 2;
    const int lc8  = (tid & 3) * 8;
    const uint32_t sdst = (uint32_t)lrow * ROWB + (tid & 3) * 16;

    const __nv_bfloat16* gA0h = ahi + (size_t)z * strideA + (size_t)(m0 + lrow) * K + lc8;
    const __nv_bfloat16* gA0l = alo + (size_t)z * strideA + (size_t)(m0 + lrow) * K + lc8;
    const __nv_bfloat16* gB0h = bhi + (size_t)(z >> bshift) * strideB + (size_t)(n0 + lrow) * K + lc8;
    const __nv_bfloat16* gB0l = blo + (size_t)(z >> bshift) * strideB + (size_t)(n0 + lrow) * K + lc8;
    const size_t rstep = (size_t)64 * K;

    // ldmatrix per-lane address offsets (within a tile)
    const uint32_t aoff = (uint32_t)(wm0 + (lane & 15)) * ROWB + ((lane >> 4) * 8) * 2;
    const uint32_t boff = (uint32_t)(wn0 + (lane & 7) + (lane >> 4) * 8) * ROWB
                        + (((lane >> 3) & 1) * 8) * 2;

    float* C = cbase + (size_t)z * strideC + (size_t)m0 * ldc + n0;

    float acc[4][4][4];
    #pragma unroll
    for (int i = 0; i < 4; ++i)
        #pragma unroll
        for (int j = 0; j < 4; ++j)
            #pragma unroll
            for (int q = 0; q < 4; ++q) acc[i][j][q] = 0.f;

    const int nch = K / KC;

    // issue chunk 0 into buffer 0
    {
        const uint32_t db = sb;
        cpa16(db + 0 * TILE_SB + sdst, gA0h);
        cpa16(db + 0 * TILE_SB + sdst + 64 * ROWB, gA0h + rstep);
        cpa16(db + 1 * TILE_SB + sdst, gA0l);
        cpa16(db + 1 * TILE_SB + sdst + 64 * ROWB, gA0l + rstep);
        cpa16(db + 2 * TILE_SB + sdst, gB0h);
        cpa16(db + 2 * TILE_SB + sdst + 64 * ROWB, gB0h + rstep);
        cpa16(db + 3 * TILE_SB + sdst, gB0l);
        cpa16(db + 3 * TILE_SB + sdst + 64 * ROWB, gB0l + rstep);
        cpa_commit();
    }

    for (int ch = 0; ch < nch; ++ch) {
        const uint32_t cb = sb + (uint32_t)(ch & 1) * BUF_SB;
        if (ch + 1 < nch) {
            const uint32_t db = sb + (uint32_t)((ch + 1) & 1) * BUF_SB;
            const int o = (ch + 1) * KC;
            cpa16(db + 0 * TILE_SB + sdst, gA0h + o);
            cpa16(db + 0 * TILE_SB + sdst + 64 * ROWB, gA0h + o + rstep);
            cpa16(db + 1 * TILE_SB + sdst, gA0l + o);
            cpa16(db + 1 * TILE_SB + sdst + 64 * ROWB, gA0l + o + rstep);
            cpa16(db + 2 * TILE_SB + sdst, gB0h + o);
            cpa16(db + 2 * TILE_SB + sdst + 64 * ROWB, gB0h + o + rstep);
            cpa16(db + 3 * TILE_SB + sdst, gB0l + o);
            cpa16(db + 3 * TILE_SB + sdst + 64 * ROWB, gB0l + o + rstep);
            cpa_commit();
            cpa_wait<1>();
        } else {
            cpa_wait<0>();
        }
        __syncthreads();

        const uint32_t ah_b = cb + 0 * TILE_SB + aoff;
        const uint32_t al_b = cb + 1 * TILE_SB + aoff;
        const uint32_t bh_b = cb + 2 * TILE_SB + boff;
        const uint32_t bl_b = cb + 3 * TILE_SB + boff;

        #pragma unroll
        for (int s = 0; s < 2; ++s) {
            uint32_t bh[4][2], bl[4][2];
            #pragma unroll
            for (int g = 0; g < 2; ++g) {
                uint32_t r[4];
                ldmx4(r, bh_b + (uint32_t)g * (16 * ROWB) + s * 32);
                bh[2 * g][0] = r[0]; bh[2 * g][1] = r[1];
                bh[2 * g + 1][0] = r[2]; bh[2 * g + 1][1] = r[3];
                ldmx4(r, bl_b + (uint32_t)g * (16 * ROWB) + s * 32);
                bl[2 * g][0] = r[0]; bl[2 * g][1] = r[1];
                bl[2 * g + 1][0] = r[2]; bl[2 * g + 1][1] = r[3];
            }
            #pragma unroll
            for (int mf = 0; mf < 4; ++mf) {
                uint32_t a_h[4], a_l[4];
                ldmx4(a_h, ah_b + (uint32_t)mf * (16 * ROWB) + s * 32);
                ldmx4(a_l, al_b + (uint32_t)mf * (16 * ROWB) + s * 32);
                // term-major order: same-acc MMAs separated by 3 independents
                #pragma unroll
                for (int nf = 0; nf < 4; ++nf)
                    mma16816(acc[mf][nf], a_h, bh[nf][0], bh[nf][1]);
                #pragma unroll
                for (int nf = 0; nf < 4; ++nf)
                    mma16816(acc[mf][nf], a_h, bl[nf][0], bl[nf][1]);
                #pragma unroll
                for (int nf = 0; nf < 4; ++nf)
                    mma16816(acc[mf][nf], a_l, bh[nf][0], bh[nf][1]);
            }
        }
        __syncthreads();
    }

    // epilogue
    #pragma unroll
    for (int mf = 0; mf < 4; ++mf) {
        const int rr = wm0 + mf * 16 + gid;
        #pragma unroll
        for (int nf = 0; nf < 4; ++nf) {
            const int cc = wn0 + nf * 8 + 2 * tig;
            float2 v0, v1;
            v0.x = acc[mf][nf][0]; v0.y = acc[mf][nf][1];
            v1.x = acc[mf][nf][2]; v1.y = acc[mf][nf][3];
            *(float2*)(C + (size_t)rr * ldc + cc)       = v0;
            *(float2*)(C + (size_t)(rr + 8) * ldc + cc) = v1;
        }
    }
}

// ---------------------------------------------------------------------------
// Fused softmax + transpose/split: normalize p in place AND emit pT hi/lo.
// Block: 256 threads, 32 columns (n) x 8-way k split.
// ---------------------------------------------------------------------------
__global__ __launch_bounds__(256) void softmax_pt_kernel(float* __restrict__ p)
{
    const int b  = blockIdx.y;
    const int n0 = blockIdx.x * 32;
    float* col = p + (size_t)b * THW_ * HW_ + n0;

    const int tid = threadIdx.x;
    const int nn = tid & 31;
    const int kk = tid >> 5;   // 0..7

    // pass 1: online max/sum per column
    float m = -CUDART_INF_F, s = 0.f;
    for (int k = kk; k < THW_; k += 8) {
        const float x = col[(size_t)k * HW_ + nn];
        const float nm = fmaxf(m, x);
        s = s * __expf(m - nm) + __expf(x - nm);
        m = nm;
    }

    __shared__ float sm[8][32], ss[8][32];
    sm[kk][nn] = m;
    ss[kk][nn] = s;
    __syncthreads();

    float M = -CUDART_INF_F;
    #pragma unroll
    for (int i = 0; i < 8; ++i) M = fmaxf(M, sm[i][nn]);
    float S = 0.f;
    #pragma unroll
    for (int i = 0; i < 8; ++i) S += ss[i][nn] * __expf(sm[i][nn] - M);
    const float rinv = 1.0f / S;
    __syncthreads();

    // pass 2: normalize in place + stage transposed bf16 hi/lo tiles
    __shared__ __align__(16) __nv_bfloat16 thi[32][72];  // 72-elem stride: aligned + spread
    __shared__ __align__(16) __nv_bfloat16 tlo[32][72];

    const int wrow = tid >> 3;            // 0..31 (n row for output)
    const int wseg = (tid & 7) * 8;       // k segment within 64-chunk
    const size_t gbase = ((size_t)b * HW_ + n0) * THW_;

    for (int k0 = 0; k0 < THW_; k0 += 64) {
        __align__(16) __nv_bfloat16 hbuf[8], lbuf[8];
        #pragma unroll
        for (int j = 0; j < 8; ++j) {
            const int k = k0 + kk * 8 + j;
            const size_t idx = (size_t)k * HW_ + nn;
            const float e = __expf(col[idx] - M) * rinv;
            col[idx] = e;
            const __nv_bfloat16 h = __float2bfloat16(e);
            hbuf[j] = h;
            lbuf[j] = __float2bfloat16(e - __bfloat162float(h));
        }
        *(uint4*)&thi[nn][kk * 8] = *(const uint4*)hbuf;
        *(uint4*)&tlo[nn][kk * 8] = *(const uint4*)lbuf;
        __syncthreads();

        const size_t go = gbase + (size_t)wrow * THW_ + k0 + wseg;
        *(uint4*)(g_pT_hi + go) = *(const uint4*)&thi[wrow][wseg];
        *(uint4*)(g_pT_lo + go) = *(const uint4*)&tlo[wrow][wseg];
        __syncthreads();
    }
}

// ---------------------------------------------------------------------------
// Concat epilogue: mem_out[b, 512:1024, :] = q_out[b]
// ---------------------------------------------------------------------------
__global__ __launch_bounds__(256) void copy_qout_kernel(
    const float4* __restrict__ q_out, float4* __restrict__ mem_out)
{
    const int i = blockIdx.x * 256 + threadIdx.x;
    const int per_b = Do_ * HW_ / 4;
    if (i >= B_ * per_b) return;
    const int b = i / per_b;
    const int r = i - b * per_b;
    mem_out[(size_t)b * (2 * Do_ * HW_ / 4) + per_b + r] = q_out[i];
}

// ---------------------------------------------------------------------------
extern "C" void kernel_launch(void* const* d_in, const int* in_sizes, int n_in,
                              void* d_out, int out_size)
{
    const float* m_in  = (const float*)d_in[0];
    const float* m_out = (const float*)d_in[1];
    const float* q_in  = (const float*)d_in[2];
    const float* q_out = (const float*)d_in[3];

    float* out     = (float*)d_out;
    float* mem_out = out;
    float* p       = out + (size_t)B_ * 2 * Do_ * HW_;

    cudaFuncSetAttribute(gemm_bf16s, cudaFuncAttributeMaxDynamicSharedMemorySize, GSMEM);

    // 1. split-convert operands (transpose to K-major where needed)
    conv_mo_kernel<<<(B_ * Do_ * THW_ / 4 + 255) / 256, 256>>>((const float4*)m_out);
    dim3 tb(32, 8);
    tconv_kernel<<<dim3(32, 4, 32), tb>>>(m_in, 128, 1024, 1.0f, 0);
    tconv_kernel<<<dim3(32, 4, 8),  tb>>>(q_in, 128, 1024, SCALE_, 1);

    // 2. GEMM1: scores -> p region of d_out
    gemm_bf16s<<<dim3(8, 8, 32), 256, GSMEM>>>(
        p, 128, 1024,
        (unsigned long long)1024 * 128, (unsigned long long)1024 * 128,
        (unsigned long long)HW_ * HW_, 2, 0);

    // 3. fused softmax (in place) + pT split/transpose
    dim3 gs(HW_ / 32, B_);
    softmax_pt_kernel<<<gs, 256>>>(p);

    // 4. GEMM2: mem -> mem_out channels [0:512]
    gemm_bf16s<<<dim3(4, 8, 8), 256, GSMEM>>>(
        mem_out, 4096, 1024,
        (unsigned long long)512 * 4096, (unsigned long long)1024 * 4096,
        (unsigned long long)1024 * 1024, 0, 1);

    // 5. concat q_out
    copy_qout_kernel<<<(B_ * Do_ * HW_ / 4 + 255) / 256, 256>>>(
        (const float4*)q_out, (float4*)mem_out);
}

// round 6
// speedup vs baseline: 1.3821x; 1.3821x over previous
#include <cuda_runtime.h>
#include <cuda_bf16.h>
#include <math_constants.h>
#include <stdint.h>

#define B_   8
#define T_   4
#define De_  128
#define Do_  512
#define HW_  1024
#define THW_ 4096

#define SCALE_ 0.08838834764831843f   // 1/sqrt(128)

// ---------------------------------------------------------------------------
// Static scratch: bf16 split (hi/lo) operands, K-major layouts.
// ---------------------------------------------------------------------------
__device__ __align__(256) __nv_bfloat16 g_miT_hi[(size_t)32 * 1024 * 128];  // [bt][m][k]
__device__ __align__(256) __nv_bfloat16 g_miT_lo[(size_t)32 * 1024 * 128];
__device__ __align__(256) __nv_bfloat16 g_qiT_hi[(size_t)8 * 1024 * 128];   // [b][n][k] pre-scaled
__device__ __align__(256) __nv_bfloat16 g_qiT_lo[(size_t)8 * 1024 * 128];
__device__ __align__(256) __nv_bfloat16 g_mo_hi[(size_t)8 * 512 * 4096];    // [b][d][k]
__device__ __align__(256) __nv_bfloat16 g_mo_lo[(size_t)8 * 512 * 4096];
__device__ __align__(256) __nv_bfloat16 g_pT_hi[(size_t)8 * 1024 * 4096];   // [b][n][k]
__device__ __align__(256) __nv_bfloat16 g_pT_lo[(size_t)8 * 1024 * 4096];

// ---------------------------------------------------------------------------
// Conversion kernels
// ---------------------------------------------------------------------------
__global__ __launch_bounds__(256) void conv_mo_kernel(const float4* __restrict__ src) {
    const size_t i = (size_t)blockIdx.x * 256 + threadIdx.x;
    if (i >= (size_t)B_ * Do_ * THW_ / 4) return;
    const float4 v = src[i];
    const __nv_bfloat16 h0 = __float2bfloat16(v.x);
    const __nv_bfloat16 h1 = __float2bfloat16(v.y);
    const __nv_bfloat16 h2 = __float2bfloat16(v.z);
    const __nv_bfloat16 h3 = __float2bfloat16(v.w);
    ((__nv_bfloat162*)g_mo_hi)[i * 2 + 0] = __halves2bfloat162(h0, h1);
    ((__nv_bfloat162*)g_mo_hi)[i * 2 + 1] = __halves2bfloat162(h2, h3);
    const __nv_bfloat16 l0 = __float2bfloat16(v.x - __bfloat162float(h0));
    const __nv_bfloat16 l1 = __float2bfloat16(v.y - __bfloat162float(h1));
    const __nv_bfloat16 l2 = __float2bfloat16(v.z - __bfloat162float(h2));
    const __nv_bfloat16 l3 = __float2bfloat16(v.w - __bfloat162float(h3));
    ((__nv_bfloat162*)g_mo_lo)[i * 2 + 0] = __halves2bfloat162(l0, l1);
    ((__nv_bfloat162*)g_mo_lo)[i * 2 + 1] = __halves2bfloat162(l2, l3);
}

// Transpose + split-convert: src [z][R][C] fp32 -> dst [z][C][R] bf16 hi/lo
// which: 0 = miT, 1 = qiT
__global__ __launch_bounds__(256) void tconv_kernel(const float* __restrict__ src,
                                                    int R, int C, float scale, int which) {
    __shared__ float tile[32][33];
    __nv_bfloat16 *dhi, *dlo;
    if (which == 0) { dhi = g_miT_hi; dlo = g_miT_lo; }
    else            { dhi = g_qiT_hi; dlo = g_qiT_lo; }

    const size_t bo = (size_t)blockIdx.z * R * C;
    const int r0 = blockIdx.y * 32, c0 = blockIdx.x * 32;
    const int x = threadIdx.x, y = threadIdx.y;   // 32 x 8

    #pragma unroll
    for (int i = 0; i < 4; ++i)
        tile[y + 8 * i][x] = src[bo + (size_t)(r0 + y + 8 * i) * C + c0 + x];
    __syncthreads();

    #pragma unroll
    for (int i = 0; i < 4; ++i) {
        const float v = tile[x][y + 8 * i] * scale;
        const __nv_bfloat16 h = __float2bfloat16(v);
        const size_t o = bo + (size_t)(c0 + y + 8 * i) * R + r0 + x;
        dhi[o] = h;
        dlo[o] = __float2bfloat16(v - __bfloat162float(h));
    }
}

// ---------------------------------------------------------------------------
// Split-bf16 GEMM via mma.sync m16n8k16 + ldmatrix + cp.async double-buffer.
// CTA tile 128x128, KC=32, 8 warps (2m x 4n), warp tile 64x32.
// Inner-loop MMA order: R4 interleaved (hh, hl, lh per nf) — measured best.
// ---------------------------------------------------------------------------
#define KC       32
#define ROWB     80                      // smem row stride bytes (40 elems)
#define TILE_SB  (128 * ROWB)            // 10240 B per tile
#define BUF_SB   (4 * TILE_SB)           // A_hi A_lo B_hi B_lo
#define GSMEM    (2 * BUF_SB)            // 81920 B

static __device__ __forceinline__ void mma16816(float* c, const uint32_t* a,
                                                uint32_t b0, uint32_t b1) {
    asm volatile(
        "mma.sync.aligned.m16n8k16.row.col.f32.bf16.bf16.f32 "
        "{%0,%1,%2,%3}, {%4,%5,%6,%7}, {%8,%9}, {%0,%1,%2,%3};"
        : "+f"(c[0]), "+f"(c[1]), "+f"(c[2]), "+f"(c[3])
        : "r"(a[0]), "r"(a[1]), "r"(a[2]), "r"(a[3]), "r"(b0), "r"(b1));
}
static __device__ __forceinline__ void ldmx4(uint32_t* r, uint32_t addr) {
    asm volatile("ldmatrix.sync.aligned.m8n8.x4.shared.b16 {%0,%1,%2,%3}, [%4];"
                 : "=r"(r[0]), "=r"(r[1]), "=r"(r[2]), "=r"(r[3]) : "r"(addr));
}
static __device__ __forceinline__ void cpa16(uint32_t dst, const void* src) {
    asm volatile("cp.async.cg.shared.global [%0], [%1], 16;" :: "r"(dst), "l"(src));
}
static __device__ __forceinline__ void cpa_commit() {
    asm volatile("cp.async.commit_group;" ::: "memory");
}
template <int N> static __device__ __forceinline__ void cpa_wait() {
    asm volatile("cp.async.wait_group %0;" :: "n"(N) : "memory");
}

__global__ __launch_bounds__(256, 2) void gemm_bf16s(
    float* __restrict__ cbase, int K, int ldc,
    unsigned long long strideA, unsigned long long strideB,
    unsigned long long strideC, int bshift, int which)
{
    extern __shared__ __align__(16) char smem[];
    const uint32_t sb = (uint32_t)__cvta_generic_to_shared(smem);

    const int tid  = threadIdx.x;
    const int wid  = tid >> 5, lane = tid & 31;
    const int gid  = lane >> 2, tig = lane & 3;
    const int wm0  = (wid & 1) * 64;
    const int wn0  = (wid >> 1) * 32;
    const int z    = blockIdx.z;
    const int m0   = blockIdx.x * 128;
    const int n0   = blockIdx.y * 128;

    const __nv_bfloat16 *ahi, *alo, *bhi, *blo;
    if (which == 0) { ahi = g_miT_hi; alo = g_miT_lo; bhi = g_qiT_hi; blo = g_qiT_lo; }
    else            { ahi = g_mo_hi;  alo = g_mo_lo;  bhi = g_pT_hi;  blo = g_pT_lo;  }

    // cp.async loader mapping: thread t -> rows (t>>2, t>>2+64), 16B col chunk (t&3)
    const int lrow = tid >> 2;
    const int lc8  = (tid & 3) * 8;
    const uint32_t sdst = (uint32_t)lrow * ROWB + (tid & 3) * 16;

    const __nv_bfloat16* gA0h = ahi + (size_t)z * strideA + (size_t)(m0 + lrow) * K + lc8;
    const __nv_bfloat16* gA0l = alo + (size_t)z * strideA + (size_t)(m0 + lrow) * K + lc8;
    const __nv_bfloat16* gB0h = bhi + (size_t)(z >> bshift) * strideB + (size_t)(n0 + lrow) * K + lc8;
    const __nv_bfloat16* gB0l = blo + (size_t)(z >> bshift) * strideB + (size_t)(n0 + lrow) * K + lc8;
    const size_t rstep = (size_t)64 * K;

    // ldmatrix per-lane address offsets (within a tile)
    const uint32_t aoff = (uint32_t)(wm0 + (lane & 15)) * ROWB + ((lane >> 4) * 8) * 2;
    const uint32_t boff = (uint32_t)(wn0 + (lane & 7) + (lane >> 4) * 8) * ROWB
                        + (((lane >> 3) & 1) * 8) * 2;

    float* C = cbase + (size_t)z * strideC + (size_t)m0 * ldc + n0;

    float acc[4][4][4];
    #pragma unroll
    for (int i = 0; i < 4; ++i)
        #pragma unroll
        for (int j = 0; j < 4; ++j)
            #pragma unroll
            for (int q = 0; q < 4; ++q) acc[i][j][q] = 0.f;

    const int nch = K / KC;

    // issue chunk 0 into buffer 0
    {
        const uint32_t db = sb;
        cpa16(db + 0 * TILE_SB + sdst, gA0h);
        cpa16(db + 0 * TILE_SB + sdst + 64 * ROWB, gA0h + rstep);
        cpa16(db + 1 * TILE_SB + sdst, gA0l);
        cpa16(db + 1 * TILE_SB + sdst + 64 * ROWB, gA0l + rstep);
        cpa16(db + 2 * TILE_SB + sdst, gB0h);
        cpa16(db + 2 * TILE_SB + sdst + 64 * ROWB, gB0h + rstep);
        cpa16(db + 3 * TILE_SB + sdst, gB0l);
        cpa16(db + 3 * TILE_SB + sdst + 64 * ROWB, gB0l + rstep);
        cpa_commit();
    }

    for (int ch = 0; ch < nch; ++ch) {
        const uint32_t cb = sb + (uint32_t)(ch & 1) * BUF_SB;
        if (ch + 1 < nch) {
            const uint32_t db = sb + (uint32_t)((ch + 1) & 1) * BUF_SB;
            const int o = (ch + 1) * KC;
            cpa16(db + 0 * TILE_SB + sdst, gA0h + o);
            cpa16(db + 0 * TILE_SB + sdst + 64 * ROWB, gA0h + o + rstep);
            cpa16(db + 1 * TILE_SB + sdst, gA0l + o);
            cpa16(db + 1 * TILE_SB + sdst + 64 * ROWB, gA0l + o + rstep);
            cpa16(db + 2 * TILE_SB + sdst, gB0h + o);
            cpa16(db + 2 * TILE_SB + sdst + 64 * ROWB, gB0h + o + rstep);
            cpa16(db + 3 * TILE_SB + sdst, gB0l + o);
            cpa16(db + 3 * TILE_SB + sdst + 64 * ROWB, gB0l + o + rstep);
            cpa_commit();
            cpa_wait<1>();
        } else {
            cpa_wait<0>();
        }
        __syncthreads();

        const uint32_t ah_b = cb + 0 * TILE_SB + aoff;
        const uint32_t al_b = cb + 1 * TILE_SB + aoff;
        const uint32_t bh_b = cb + 2 * TILE_SB + boff;
        const uint32_t bl_b = cb + 3 * TILE_SB + boff;

        #pragma unroll
        for (int s = 0; s < 2; ++s) {
            uint32_t bh[4][2], bl[4][2];
            #pragma unroll
            for (int g = 0; g < 2; ++g) {
                uint32_t r[4];
                ldmx4(r, bh_b + (uint32_t)g * (16 * ROWB) + s * 32);
                bh[2 * g][0] = r[0]; bh[2 * g][1] = r[1];
                bh[2 * g + 1][0] = r[2]; bh[2 * g + 1][1] = r[3];
                ldmx4(r, bl_b + (uint32_t)g * (16 * ROWB) + s * 32);
                bl[2 * g][0] = r[0]; bl[2 * g][1] = r[1];
                bl[2 * g + 1][0] = r[2]; bl[2 * g + 1][1] = r[3];
            }
            #pragma unroll
            for (int mf = 0; mf < 4; ++mf) {
                uint32_t a_h[4], a_l[4];
                ldmx4(a_h, ah_b + (uint32_t)mf * (16 * ROWB) + s * 32);
                ldmx4(a_l, al_b + (uint32_t)mf * (16 * ROWB) + s * 32);
                #pragma unroll
                for (int nf = 0; nf < 4; ++nf) {
                    mma16816(acc[mf][nf], a_h, bh[nf][0], bh[nf][1]);
                    mma16816(acc[mf][nf], a_h, bl[nf][0], bl[nf][1]);
                    mma16816(acc[mf][nf], a_l, bh[nf][0], bh[nf][1]);
                }
            }
        }
        __syncthreads();
    }

    // epilogue
    #pragma unroll
    for (int mf = 0; mf < 4; ++mf) {
        const int rr = wm0 + mf * 16 + gid;
        #pragma unroll
        for (int nf = 0; nf < 4; ++nf) {
            const int cc = wn0 + nf * 8 + 2 * tig;
            float2 v0, v1;
            v0.x = acc[mf][nf][0]; v0.y = acc[mf][nf][1];
            v1.x = acc[mf][nf][2]; v1.y = acc[mf][nf][3];
            *(float2*)(C + (size_t)rr * ldc + cc)       = v0;
            *(float2*)(C + (size_t)(rr + 8) * ldc + cc) = v1;
        }
    }
}

// ---------------------------------------------------------------------------
// Fused softmax + transpose/split: normalize p in place AND emit pT hi/lo.
// Block: 256 threads, 32 columns (n) x 8-way k split.
// ---------------------------------------------------------------------------
__global__ __launch_bounds__(256) void softmax_pt_kernel(float* __restrict__ p)
{
    const int b  = blockIdx.y;
    const int n0 = blockIdx.x * 32;
    float* col = p + (size_t)b * THW_ * HW_ + n0;

    const int tid = threadIdx.x;
    const int nn = tid & 31;
    const int kk = tid >> 5;   // 0..7

    // pass 1: online max/sum per column
    float m = -CUDART_INF_F, s = 0.f;
    for (int k = kk; k < THW_; k += 8) {
        const float x = col[(size_t)k * HW_ + nn];
        const float nm = fmaxf(m, x);
        s = s * __expf(m - nm) + __expf(x - nm);
        m = nm;
    }

    __shared__ float sm[8][32], ss[8][32];
    sm[kk][nn] = m;
    ss[kk][nn] = s;
    __syncthreads();

    float M = -CUDART_INF_F;
    #pragma unroll
    for (int i = 0; i < 8; ++i) M = fmaxf(M, sm[i][nn]);
    float S = 0.f;
    #pragma unroll
    for (int i = 0; i < 8; ++i) S += ss[i][nn] * __expf(sm[i][nn] - M);
    const float rinv = 1.0f / S;
    __syncthreads();

    // pass 2: normalize in place + stage transposed bf16 hi/lo tiles
    __shared__ __align__(16) __nv_bfloat16 thi[32][72];
    __shared__ __align__(16) __nv_bfloat16 tlo[32][72];

    const int wrow = tid >> 3;            // 0..31 (n row for output)
    const int wseg = (tid & 7) * 8;       // k segment within 64-chunk
    const size_t gbase = ((size_t)b * HW_ + n0) * THW_;

    for (int k0 = 0; k0 < THW_; k0 += 64) {
        __align__(16) __nv_bfloat16 hbuf[8], lbuf[8];
        #pragma unroll
        for (int j = 0; j < 8; ++j) {
            const int k = k0 + kk * 8 + j;
            const size_t idx = (size_t)k * HW_ + nn;
            const float e = __expf(col[idx] - M) * rinv;
            col[idx] = e;
            const __nv_bfloat16 h = __float2bfloat16(e);
            hbuf[j] = h;
            lbuf[j] = __float2bfloat16(e - __bfloat162float(h));
        }
        *(uint4*)&thi[nn][kk * 8] = *(const uint4*)hbuf;
        *(uint4*)&tlo[nn][kk * 8] = *(const uint4*)lbuf;
        __syncthreads();

        const size_t go = gbase + (size_t)wrow * THW_ + k0 + wseg;
        *(uint4*)(g_pT_hi + go) = *(const uint4*)&thi[wrow][wseg];
        *(uint4*)(g_pT_lo + go) = *(const uint4*)&tlo[wrow][wseg];
        __syncthreads();
    }
}

// ---------------------------------------------------------------------------
// Concat epilogue: mem_out[b, 512:1024, :] = q_out[b]
// ---------------------------------------------------------------------------
__global__ __launch_bounds__(256) void copy_qout_kernel(
    const float4* __restrict__ q_out, float4* __restrict__ mem_out)
{
    const int i = blockIdx.x * 256 + threadIdx.x;
    const int per_b = Do_ * HW_ / 4;
    if (i >= B_ * per_b) return;
    const int b = i / per_b;
    const int r = i - b * per_b;
    mem_out[(size_t)b * (2 * Do_ * HW_ / 4) + per_b + r] = q_out[i];
}

// ---------------------------------------------------------------------------
extern "C" void kernel_launch(void* const* d_in, const int* in_sizes, int n_in,
                              void* d_out, int out_size)
{
    const float* m_in  = (const float*)d_in[0];
    const float* m_out = (const float*)d_in[1];
    const float* q_in  = (const float*)d_in[2];
    const float* q_out = (const float*)d_in[3];

    float* out     = (float*)d_out;
    float* mem_out = out;
    float* p       = out + (size_t)B_ * 2 * Do_ * HW_;

    cudaFuncSetAttribute(gemm_bf16s, cudaFuncAttributeMaxDynamicSharedMemorySize, GSMEM);

    // 1. split-convert operands (transpose to K-major where needed)
    conv_mo_kernel<<<(B_ * Do_ * THW_ / 4 + 255) / 256, 256>>>((const float4*)m_out);
    dim3 tb(32, 8);
    tconv_kernel<<<dim3(32, 4, 32), tb>>>(m_in, 128, 1024, 1.0f, 0);
    tconv_kernel<<<dim3(32, 4, 8),  tb>>>(q_in, 128, 1024, SCALE_, 1);

    // 2. GEMM1: scores -> p region of d_out
    gemm_bf16s<<<dim3(8, 8, 32), 256, GSMEM>>>(
        p, 128, 1024,
        (unsigned long long)1024 * 128, (unsigned long long)1024 * 128,
        (unsigned long long)HW_ * HW_, 2, 0);

    // 3. fused softmax (in place) + pT split/transpose
    dim3 gs(HW_ / 32, B_);
    softmax_pt_kernel<<<gs, 256>>>(p);

    // 4. GEMM2: mem -> mem_out channels [0:512]
    gemm_bf16s<<<dim3(4, 8, 8), 256, GSMEM>>>(
        mem_out, 4096, 1024,
        (unsigned long long)512 * 4096, (unsigned long long)1024 * 4096,
        (unsigned long long)1024 * 1024, 0, 1);

    // 5. concat q_out
    copy_qout_kernel<<<(B_ * Do_ * HW_ / 4 + 255) / 256, 256>>>(
        (const float4*)q_out, (float4*)mem_out);
}

// round 7
// speedup vs baseline: 1.9805x; 1.4330x over previous
#include <cuda_runtime.h>
#include <cuda_fp16.h>
#include <math_constants.h>
#include <stdint.h>

#define B_   8
#define T_   4
#define De_  128
#define Do_  512
#define HW_  1024
#define THW_ 4096

#define SCALE_ 0.08838834764831843f   // 1/sqrt(128)

// ---------------------------------------------------------------------------
// Static scratch: fp16 operands, K-major layouts.
// ---------------------------------------------------------------------------
__device__ __align__(256) __half g_miT[(size_t)32 * 1024 * 128];  // [bt][m][k]
__device__ __align__(256) __half g_qiT[(size_t)8 * 1024 * 128];   // [b][n][k] pre-scaled
__device__ __align__(256) __half g_mo[(size_t)8 * 512 * 4096];    // [b][d][k]
__device__ __align__(256) __half g_pT[(size_t)8 * 1024 * 4096];   // [b][n][k]

// ---------------------------------------------------------------------------
// Conversion kernels
// ---------------------------------------------------------------------------
__global__ __launch_bounds__(256) void conv_mo_kernel(const float4* __restrict__ src) {
    const size_t i = (size_t)blockIdx.x * 256 + threadIdx.x;
    if (i >= (size_t)B_ * Do_ * THW_ / 4) return;
    const float4 v = src[i];
    __half2* dst = (__half2*)g_mo;
    dst[i * 2 + 0] = __halves2half2(__float2half(v.x), __float2half(v.y));
    dst[i * 2 + 1] = __halves2half2(__float2half(v.z), __float2half(v.w));
}

// Transpose + convert: src [z][R][C] fp32 -> dst [z][C][R] fp16
// which: 0 = miT, 1 = qiT
__global__ __launch_bounds__(256) void tconv_kernel(const float* __restrict__ src,
                                                    int R, int C, float scale, int which) {
    __shared__ float tile[32][33];
    __half* dst = (which == 0) ? g_miT : g_qiT;

    const size_t bo = (size_t)blockIdx.z * R * C;
    const int r0 = blockIdx.y * 32, c0 = blockIdx.x * 32;
    const int x = threadIdx.x, y = threadIdx.y;   // 32 x 8

    #pragma unroll
    for (int i = 0; i < 4; ++i)
        tile[y + 8 * i][x] = src[bo + (size_t)(r0 + y + 8 * i) * C + c0 + x];
    __syncthreads();

    #pragma unroll
    for (int i = 0; i < 4; ++i) {
        const float v = tile[x][y + 8 * i] * scale;
        dst[bo + (size_t)(c0 + y + 8 * i) * R + r0 + x] = __float2half(v);
    }
}

// ---------------------------------------------------------------------------
// fp16 GEMM via mma.sync m16n8k16 + ldmatrix + cp.async double-buffer.
// CTA tile 128x128, KC=32, 8 warps (2m x 4n), warp tile 64x32.
//   C[m,n] = sum_k A[m,k]*B[n,k], fp32 accum.
// which: 0 = GEMM1 (A=miT, B=qiT), 1 = GEMM2 (A=mo, B=pT)
// ---------------------------------------------------------------------------
#define KC       32
#define ROWB     80                      // smem row stride bytes (40 elems)
#define TILE_SB  (128 * ROWB)            // 10240 B per tile
#define BUF_SB   (2 * TILE_SB)           // A, B
#define GSMEM    (2 * BUF_SB)            // 40960 B

static __device__ __forceinline__ void mma16816(float* c, const uint32_t* a,
                                                uint32_t b0, uint32_t b1) {
    asm volatile(
        "mma.sync.aligned.m16n8k16.row.col.f32.f16.f16.f32 "
        "{%0,%1,%2,%3}, {%4,%5,%6,%7}, {%8,%9}, {%0,%1,%2,%3};"
        : "+f"(c[0]), "+f"(c[1]), "+f"(c[2]), "+f"(c[3])
        : "r"(a[0]), "r"(a[1]), "r"(a[2]), "r"(a[3]), "r"(b0), "r"(b1));
}
static __device__ __forceinline__ void ldmx4(uint32_t* r, uint32_t addr) {
    asm volatile("ldmatrix.sync.aligned.m8n8.x4.shared.b16 {%0,%1,%2,%3}, [%4];"
                 : "=r"(r[0]), "=r"(r[1]), "=r"(r[2]), "=r"(r[3]) : "r"(addr));
}
static __device__ __forceinline__ void cpa16(uint32_t dst, const void* src) {
    asm volatile("cp.async.cg.shared.global [%0], [%1], 16;" :: "r"(dst), "l"(src));
}
static __device__ __forceinline__ void cpa_commit() {
    asm volatile("cp.async.commit_group;" ::: "memory");
}
template <int N> static __device__ __forceinline__ void cpa_wait() {
    asm volatile("cp.async.wait_group %0;" :: "n"(N) : "memory");
}

__global__ __launch_bounds__(256, 2) void gemm_fp16(
    float* __restrict__ cbase, int K, int ldc,
    unsigned long long strideA, unsigned long long strideB,
    unsigned long long strideC, int bshift, int which)
{
    extern __shared__ __align__(16) char smem[];
    const uint32_t sb = (uint32_t)__cvta_generic_to_shared(smem);

    const int tid  = threadIdx.x;
    const int wid  = tid >> 5, lane = tid & 31;
    const int gid  = lane >> 2, tig = lane & 3;
    const int wm0  = (wid & 1) * 64;
    const int wn0  = (wid >> 1) * 32;
    const int z    = blockIdx.z;
    const int m0   = blockIdx.x * 128;
    const int n0   = blockIdx.y * 128;

    const __half* A = (which == 0) ? g_miT : g_mo;
    const __half* Bm = (which == 0) ? g_qiT : g_pT;

    // cp.async loader mapping: thread t -> rows (t>>2, t>>2+64), 16B col chunk (t&3)
    const int lrow = tid >> 2;
    const int lc8  = (tid & 3) * 8;
    const uint32_t sdst = (uint32_t)lrow * ROWB + (tid & 3) * 16;

    const __half* gA = A  + (size_t)z * strideA + (size_t)(m0 + lrow) * K + lc8;
    const __half* gB = Bm + (size_t)(z >> bshift) * strideB + (size_t)(n0 + lrow) * K + lc8;
    const size_t rstep = (size_t)64 * K;

    // ldmatrix per-lane address offsets (within a tile)
    const uint32_t aoff = (uint32_t)(wm0 + (lane & 15)) * ROWB + ((lane >> 4) * 8) * 2;
    const uint32_t boff = (uint32_t)(wn0 + (lane & 7) + (lane >> 4) * 8) * ROWB
                        + (((lane >> 3) & 1) * 8) * 2;

    float* C = cbase + (size_t)z * strideC + (size_t)m0 * ldc + n0;

    float acc[4][4][4];
    #pragma unroll
    for (int i = 0; i < 4; ++i)
        #pragma unroll
        for (int j = 0; j < 4; ++j)
            #pragma unroll
            for (int q = 0; q < 4; ++q) acc[i][j][q] = 0.f;

    const int nch = K / KC;

    // issue chunk 0 into buffer 0
    {
        cpa16(sb + 0 * TILE_SB + sdst, gA);
        cpa16(sb + 0 * TILE_SB + sdst + 64 * ROWB, gA + rstep);
        cpa16(sb + 1 * TILE_SB + sdst, gB);
        cpa16(sb + 1 * TILE_SB + sdst + 64 * ROWB, gB + rstep);
        cpa_commit();
    }

    for (int ch = 0; ch < nch; ++ch) {
        const uint32_t cb = sb + (uint32_t)(ch & 1) * BUF_SB;
        if (ch + 1 < nch) {
            const uint32_t db = sb + (uint32_t)((ch + 1) & 1) * BUF_SB;
            const int o = (ch + 1) * KC;
            cpa16(db + 0 * TILE_SB + sdst, gA + o);
            cpa16(db + 0 * TILE_SB + sdst + 64 * ROWB, gA + o + rstep);
            cpa16(db + 1 * TILE_SB + sdst, gB + o);
            cpa16(db + 1 * TILE_SB + sdst + 64 * ROWB, gB + o + rstep);
            cpa_commit();
            cpa_wait<1>();
        } else {
            cpa_wait<0>();
        }
        __syncthreads();

        const uint32_t a_b = cb + 0 * TILE_SB + aoff;
        const uint32_t b_b = cb + 1 * TILE_SB + boff;

        #pragma unroll
        for (int s = 0; s < 2; ++s) {
            uint32_t bf[4][2];
            #pragma unroll
            for (int g = 0; g < 2; ++g) {
                uint32_t r[4];
                ldmx4(r, b_b + (uint32_t)g * (16 * ROWB) + s * 32);
                bf[2 * g][0] = r[0]; bf[2 * g][1] = r[1];
                bf[2 * g + 1][0] = r[2]; bf[2 * g + 1][1] = r[3];
            }
            #pragma unroll
            for (int mf = 0; mf < 4; ++mf) {
                uint32_t af[4];
                ldmx4(af, a_b + (uint32_t)mf * (16 * ROWB) + s * 32);
                #pragma unroll
                for (int nf = 0; nf < 4; ++nf)
                    mma16816(acc[mf][nf], af, bf[nf][0], bf[nf][1]);
            }
        }
        __syncthreads();
    }

    // epilogue
    #pragma unroll
    for (int mf = 0; mf < 4; ++mf) {
        const int rr = wm0 + mf * 16 + gid;
        #pragma unroll
        for (int nf = 0; nf < 4; ++nf) {
            const int cc = wn0 + nf * 8 + 2 * tig;
            float2 v0, v1;
            v0.x = acc[mf][nf][0]; v0.y = acc[mf][nf][1];
            v1.x = acc[mf][nf][2]; v1.y = acc[mf][nf][3];
            *(float2*)(C + (size_t)rr * ldc + cc)       = v0;
            *(float2*)(C + (size_t)(rr + 8) * ldc + cc) = v1;
        }
    }
}

// ---------------------------------------------------------------------------
// Fused softmax + transpose/convert: normalize p in place AND emit pT fp16.
// Block: 256 threads, 32 columns (n) x 8-way k split.
// ---------------------------------------------------------------------------
__global__ __launch_bounds__(256) void softmax_pt_kernel(float* __restrict__ p)
{
    const int b  = blockIdx.y;
    const int n0 = blockIdx.x * 32;
    float* col = p + (size_t)b * THW_ * HW_ + n0;

    const int tid = threadIdx.x;
    const int nn = tid & 31;
    const int kk = tid >> 5;   // 0..7

    // pass 1: online max/sum per column
    float m = -CUDART_INF_F, s = 0.f;
    for (int k = kk; k < THW_; k += 8) {
        const float x = col[(size_t)k * HW_ + nn];
        const float nm = fmaxf(m, x);
        s = s * __expf(m - nm) + __expf(x - nm);
        m = nm;
    }

    __shared__ float sm[8][32], ss[8][32];
    sm[kk][nn] = m;
    ss[kk][nn] = s;
    __syncthreads();

    float M = -CUDART_INF_F;
    #pragma unroll
    for (int i = 0; i < 8; ++i) M = fmaxf(M, sm[i][nn]);
    float S = 0.f;
    #pragma unroll
    for (int i = 0; i < 8; ++i) S += ss[i][nn] * __expf(sm[i][nn] - M);
    const float rinv = 1.0f / S;
    __syncthreads();

    // pass 2: normalize in place + stage transposed fp16 tiles
    __shared__ __align__(16) __half thi[32][72];

    const int wrow = tid >> 3;            // 0..31 (n row for output)
    const int wseg = (tid & 7) * 8;       // k segment within 64-chunk
    const size_t gbase = ((size_t)b * HW_ + n0) * THW_;

    for (int k0 = 0; k0 < THW_; k0 += 64) {
        __align__(16) __half hbuf[8];
        #pragma unroll
        for (int j = 0; j < 8; ++j) {
            const int k = k0 + kk * 8 + j;
            const size_t idx = (size_t)k * HW_ + nn;
            const float e = __expf(col[idx] - M) * rinv;
            col[idx] = e;
            hbuf[j] = __float2half(e);
        }
        *(uint4*)&thi[nn][kk * 8] = *(const uint4*)hbuf;
        __syncthreads();

        *(uint4*)(g_pT + gbase + (size_t)wrow * THW_ + k0 + wseg) =
            *(const uint4*)&thi[wrow][wseg];
        __syncthreads();
    }
}

// ---------------------------------------------------------------------------
// Concat epilogue: mem_out[b, 512:1024, :] = q_out[b]
// ---------------------------------------------------------------------------
__global__ __launch_bounds__(256) void copy_qout_kernel(
    const float4* __restrict__ q_out, float4* __restrict__ mem_out)
{
    const int i = blockIdx.x * 256 + threadIdx.x;
    const int per_b = Do_ * HW_ / 4;
    if (i >= B_ * per_b) return;
    const int b = i / per_b;
    const int r = i - b * per_b;
    mem_out[(size_t)b * (2 * Do_ * HW_ / 4) + per_b + r] = q_out[i];
}

// ---------------------------------------------------------------------------
extern "C" void kernel_launch(void* const* d_in, const int* in_sizes, int n_in,
                              void* d_out, int out_size)
{
    const float* m_in  = (const float*)d_in[0];
    const float* m_out = (const float*)d_in[1];
    const float* q_in  = (const float*)d_in[2];
    const float* q_out = (const float*)d_in[3];

    float* out     = (float*)d_out;
    float* mem_out = out;
    float* p       = out + (size_t)B_ * 2 * Do_ * HW_;

    cudaFuncSetAttribute(gemm_fp16, cudaFuncAttributeMaxDynamicSharedMemorySize, GSMEM);

    // 1. convert operands (transpose to K-major where needed)
    conv_mo_kernel<<<(B_ * Do_ * THW_ / 4 + 255) / 256, 256>>>((const float4*)m_out);
    dim3 tb(32, 8);
    tconv_kernel<<<dim3(32, 4, 32), tb>>>(m_in, 128, 1024, 1.0f, 0);
    tconv_kernel<<<dim3(32, 4, 8),  tb>>>(q_in, 128, 1024, SCALE_, 1);

    // 2. GEMM1: scores -> p region of d_out
    gemm_fp16<<<dim3(8, 8, 32), 256, GSMEM>>>(
        p, 128, 1024,
        (unsigned long long)1024 * 128, (unsigned long long)1024 * 128,
        (unsigned long long)HW_ * HW_, 2, 0);

    // 3. fused softmax (in place) + pT convert/transpose
    dim3 gs(HW_ / 32, B_);
    softmax_pt_kernel<<<gs, 256>>>(p);

    // 4. GEMM2: mem -> mem_out channels [0:512]
    gemm_fp16<<<dim3(4, 8, 8), 256, GSMEM>>>(
        mem_out, 4096, 1024,
        (unsigned long long)512 * 4096, (unsigned long long)1024 * 4096,
        (unsigned long long)1024 * 1024, 0, 1);

    // 5. concat q_out
    copy_qout_kernel<<<(B_ * Do_ * HW_ / 4 + 255) / 256, 256>>>(
        (const float4*)q_out, (float4*)mem_out);
}

// round 8
// speedup vs baseline: 2.0718x; 1.0461x over previous
#include <cuda_runtime.h>
#include <cuda_fp16.h>
#include <math_constants.h>
#include <stdint.h>

#define B_   8
#define T_   4
#define De_  128
#define Do_  512
#define HW_  1024
#define THW_ 4096

#define SCALE_ 0.08838834764831843f   // 1/sqrt(128)

// ---------------------------------------------------------------------------
// Static scratch: fp16 operands, K-major layouts.
// ---------------------------------------------------------------------------
__device__ __align__(256) __half g_miT[(size_t)32 * 1024 * 128];  // [bt][m][k]
__device__ __align__(256) __half g_qiT[(size_t)8 * 1024 * 128];   // [b][n][k] pre-scaled
__device__ __align__(256) __half g_mo[(size_t)8 * 512 * 4096];    // [b][d][k]
__device__ __align__(256) __half g_pT[(size_t)8 * 1024 * 4096];   // [b][n][k]

// ---------------------------------------------------------------------------
// Conversion kernels
// ---------------------------------------------------------------------------
__global__ __launch_bounds__(256) void conv_mo_kernel(const float4* __restrict__ src) {
    const size_t i = (size_t)blockIdx.x * 256 + threadIdx.x;
    if (i >= (size_t)B_ * Do_ * THW_ / 4) return;
    const float4 v = src[i];
    __half2* dst = (__half2*)g_mo;
    dst[i * 2 + 0] = __halves2half2(__float2half(v.x), __float2half(v.y));
    dst[i * 2 + 1] = __halves2half2(__float2half(v.z), __float2half(v.w));
}

// Transpose + convert: src [z][R][C] fp32 -> dst [z][C][R] fp16
// which: 0 = miT, 1 = qiT
__global__ __launch_bounds__(256) void tconv_kernel(const float* __restrict__ src,
                                                    int R, int C, float scale, int which) {
    __shared__ float tile[32][33];
    __half* dst = (which == 0) ? g_miT : g_qiT;

    const size_t bo = (size_t)blockIdx.z * R * C;
    const int r0 = blockIdx.y * 32, c0 = blockIdx.x * 32;
    const int x = threadIdx.x, y = threadIdx.y;   // 32 x 8

    #pragma unroll
    for (int i = 0; i < 4; ++i)
        tile[y + 8 * i][x] = src[bo + (size_t)(r0 + y + 8 * i) * C + c0 + x];
    __syncthreads();

    #pragma unroll
    for (int i = 0; i < 4; ++i) {
        const float v = tile[x][y + 8 * i] * scale;
        dst[bo + (size_t)(c0 + y + 8 * i) * R + r0 + x] = __float2half(v);
    }
}

// ---------------------------------------------------------------------------
// fp16 GEMM: mma.sync m16n8k16 + ldmatrix.x4 + cp.async double-buffer.
// CTA tile 128x128, KC=32, 4 warps (2m x 2n), warp tile 64x64.
//   C[m,n] = sum_k A[m,k]*B[n,k], fp32 accum.
// which: 0 = GEMM1 (A=miT, B=qiT), 1 = GEMM2 (A=mo, B=pT)
// ---------------------------------------------------------------------------
#define KC       32
#define ROWB     80                      // smem row stride bytes (40 elems)
#define TILE_SB  (128 * ROWB)            // 10240 B per tile
#define BUF_SB   (2 * TILE_SB)           // A, B
#define GSMEM    (2 * BUF_SB)            // 40960 B

static __device__ __forceinline__ void mma16816(float* c, const uint32_t* a,
                                                uint32_t b0, uint32_t b1) {
    asm volatile(
        "mma.sync.aligned.m16n8k16.row.col.f32.f16.f16.f32 "
        "{%0,%1,%2,%3}, {%4,%5,%6,%7}, {%8,%9}, {%0,%1,%2,%3};"
        : "+f"(c[0]), "+f"(c[1]), "+f"(c[2]), "+f"(c[3])
        : "r"(a[0]), "r"(a[1]), "r"(a[2]), "r"(a[3]), "r"(b0), "r"(b1));
}
static __device__ __forceinline__ void ldmx4(uint32_t* r, uint32_t addr) {
    asm volatile("ldmatrix.sync.aligned.m8n8.x4.shared.b16 {%0,%1,%2,%3}, [%4];"
                 : "=r"(r[0]), "=r"(r[1]), "=r"(r[2]), "=r"(r[3]) : "r"(addr));
}
static __device__ __forceinline__ void cpa16(uint32_t dst, const void* src) {
    asm volatile("cp.async.cg.shared.global [%0], [%1], 16;" :: "r"(dst), "l"(src));
}
static __device__ __forceinline__ void cpa_commit() {
    asm volatile("cp.async.commit_group;" ::: "memory");
}
template <int N> static __device__ __forceinline__ void cpa_wait() {
    asm volatile("cp.async.wait_group %0;" :: "n"(N) : "memory");
}

__global__ __launch_bounds__(128, 2) void gemm_fp16(
    float* __restrict__ cbase, int K, int ldc,
    unsigned long long strideA, unsigned long long strideB,
    unsigned long long strideC, int bshift, int which)
{
    extern __shared__ __align__(16) char smem[];
    const uint32_t sb = (uint32_t)__cvta_generic_to_shared(smem);

    const int tid  = threadIdx.x;
    const int wid  = tid >> 5, lane = tid & 31;
    const int gid  = lane >> 2, tig = lane & 3;
    const int wm0  = (wid & 1) * 64;
    const int wn0  = (wid >> 1) * 64;
    const int z    = blockIdx.z;
    const int m0   = blockIdx.x * 128;
    const int n0   = blockIdx.y * 128;

    const __half* A  = (which == 0) ? g_miT : g_mo;
    const __half* Bm = (which == 0) ? g_qiT : g_pT;

    // cp.async loader: thread t -> rows (t>>2 + 32*i), 16B col chunk (t&3)
    const int lrow = tid >> 2;                       // 0..31
    const int lc8  = (tid & 3) * 8;
    const uint32_t sdst = (uint32_t)lrow * ROWB + (tid & 3) * 16;

    const __half* gA = A  + (size_t)z * strideA + (size_t)(m0 + lrow) * K + lc8;
    const __half* gB = Bm + (size_t)(z >> bshift) * strideB + (size_t)(n0 + lrow) * K + lc8;
    const size_t r32 = (size_t)32 * K;

    // ldmatrix per-lane address offsets (within a tile)
    const uint32_t aoff = (uint32_t)(wm0 + (lane & 15)) * ROWB + ((lane >> 4) * 8) * 2;
    const uint32_t boff = (uint32_t)(wn0 + (lane & 7) + (lane >> 4) * 8) * ROWB
                        + (((lane >> 3) & 1) * 8) * 2;

    float* C = cbase + (size_t)z * strideC + (size_t)m0 * ldc + n0;

    float acc[4][8][4];
    #pragma unroll
    for (int i = 0; i < 4; ++i)
        #pragma unroll
        for (int j = 0; j < 8; ++j)
            #pragma unroll
            for (int q = 0; q < 4; ++q) acc[i][j][q] = 0.f;

    const int nch = K / KC;

    // issue chunk 0 into buffer 0
    {
        #pragma unroll
        for (int i = 0; i < 4; ++i) {
            cpa16(sb + 0 * TILE_SB + sdst + i * (32 * ROWB), gA + i * r32);
            cpa16(sb + 1 * TILE_SB + sdst + i * (32 * ROWB), gB + i * r32);
        }
        cpa_commit();
    }

    for (int ch = 0; ch < nch; ++ch) {
        const uint32_t cb = sb + (uint32_t)(ch & 1) * BUF_SB;
        if (ch + 1 < nch) {
            const uint32_t db = sb + (uint32_t)((ch + 1) & 1) * BUF_SB;
            const int o = (ch + 1) * KC;
            #pragma unroll
            for (int i = 0; i < 4; ++i) {
                cpa16(db + 0 * TILE_SB + sdst + i * (32 * ROWB), gA + o + i * r32);
                cpa16(db + 1 * TILE_SB + sdst + i * (32 * ROWB), gB + o + i * r32);
            }
            cpa_commit();
            cpa_wait<1>();
        } else {
            cpa_wait<0>();
        }
        __syncthreads();

        const uint32_t a_b = cb + 0 * TILE_SB + aoff;
        const uint32_t b_b = cb + 1 * TILE_SB + boff;

        #pragma unroll
        for (int s = 0; s < 2; ++s) {
            uint32_t bf[8][2];
            #pragma unroll
            for (int g = 0; g < 4; ++g) {
                uint32_t r[4];
                ldmx4(r, b_b + (uint32_t)g * (16 * ROWB) + s * 32);
                bf[2 * g][0] = r[0]; bf[2 * g][1] = r[1];
                bf[2 * g + 1][0] = r[2]; bf[2 * g + 1][1] = r[3];
            }
            #pragma unroll
            for (int mf = 0; mf < 4; ++mf) {
                uint32_t af[4];
                ldmx4(af, a_b + (uint32_t)mf * (16 * ROWB) + s * 32);
                #pragma unroll
                for (int nf = 0; nf < 8; ++nf)
                    mma16816(acc[mf][nf], af, bf[nf][0], bf[nf][1]);
            }
        }
        __syncthreads();
    }

    // epilogue
    #pragma unroll
    for (int mf = 0; mf < 4; ++mf) {
        const int rr = wm0 + mf * 16 + gid;
        #pragma unroll
        for (int nf = 0; nf < 8; ++nf) {
            const int cc = wn0 + nf * 8 + 2 * tig;
            float2 v0, v1;
            v0.x = acc[mf][nf][0]; v0.y = acc[mf][nf][1];
            v1.x = acc[mf][nf][2]; v1.y = acc[mf][nf][3];
            *(float2*)(C + (size_t)rr * ldc + cc)       = v0;
            *(float2*)(C + (size_t)(rr + 8) * ldc + cc) = v1;
        }
    }
}

// ---------------------------------------------------------------------------
// Fused softmax + transpose/convert: normalize p in place AND emit pT fp16.
// Block: 256 threads, 32 columns (n) x 8-way k split.
// ---------------------------------------------------------------------------
__global__ __launch_bounds__(256) void softmax_pt_kernel(float* __restrict__ p)
{
    const int b  = blockIdx.y;
    const int n0 = blockIdx.x * 32;
    float* col = p + (size_t)b * THW_ * HW_ + n0;

    const int tid = threadIdx.x;
    const int nn = tid & 31;
    const int kk = tid >> 5;   // 0..7

    // pass 1: online max/sum per column
    float m = -CUDART_INF_F, s = 0.f;
    for (int k = kk; k < THW_; k += 8) {
        const float x = col[(size_t)k * HW_ + nn];
        const float nm = fmaxf(m, x);
        s = s * __expf(m - nm) + __expf(x - nm);
        m = nm;
    }

    __shared__ float sm[8][32], ss[8][32];
    sm[kk][nn] = m;
    ss[kk][nn] = s;
    __syncthreads();

    float M = -CUDART_INF_F;
    #pragma unroll
    for (int i = 0; i < 8; ++i) M = fmaxf(M, sm[i][nn]);
    float S = 0.f;
    #pragma unroll
    for (int i = 0; i < 8; ++i) S += ss[i][nn] * __expf(sm[i][nn] - M);
    const float rinv = 1.0f / S;
    __syncthreads();

    // pass 2: normalize in place + stage transposed fp16 tiles
    __shared__ __align__(16) __half thi[32][72];

    const int wrow = tid >> 3;            // 0..31 (n row for output)
    const int wseg = (tid & 7) * 8;       // k segment within 64-chunk
    const size_t gbase = ((size_t)b * HW_ + n0) * THW_;

    for (int k0 = 0; k0 < THW_; k0 += 64) {
        __align__(16) __half hbuf[8];
        #pragma unroll
        for (int j = 0; j < 8; ++j) {
            const int k = k0 + kk * 8 + j;
            const size_t idx = (size_t)k * HW_ + nn;
            const float e = __expf(col[idx] - M) * rinv;
            col[idx] = e;
            hbuf[j] = __float2half(e);
        }
        *(uint4*)&thi[nn][kk * 8] = *(const uint4*)hbuf;
        __syncthreads();

        *(uint4*)(g_pT + gbase + (size_t)wrow * THW_ + k0 + wseg) =
            *(const uint4*)&thi[wrow][wseg];
        __syncthreads();
    }
}

// ---------------------------------------------------------------------------
// Concat epilogue: mem_out[b, 512:1024, :] = q_out[b]
// ---------------------------------------------------------------------------
__global__ __launch_bounds__(256) void copy_qout_kernel(
    const float4* __restrict__ q_out, float4* __restrict__ mem_out)
{
    const int i = blockIdx.x * 256 + threadIdx.x;
    const int per_b = Do_ * HW_ / 4;
    if (i >= B_ * per_b) return;
    const int b = i / per_b;
    const int r = i - b * per_b;
    mem_out[(size_t)b * (2 * Do_ * HW_ / 4) + per_b + r] = q_out[i];
}

// ---------------------------------------------------------------------------
extern "C" void kernel_launch(void* const* d_in, const int* in_sizes, int n_in,
                              void* d_out, int out_size)
{
    const float* m_in  = (const float*)d_in[0];
    const float* m_out = (const float*)d_in[1];
    const float* q_in  = (const float*)d_in[2];
    const float* q_out = (const float*)d_in[3];

    float* out     = (float*)d_out;
    float* mem_out = out;
    float* p       = out + (size_t)B_ * 2 * Do_ * HW_;

    cudaFuncSetAttribute(gemm_fp16, cudaFuncAttributeMaxDynamicSharedMemorySize, GSMEM);

    // 1. convert operands (transpose to K-major where needed)
    conv_mo_kernel<<<(B_ * Do_ * THW_ / 4 + 255) / 256, 256>>>((const float4*)m_out);
    dim3 tb(32, 8);
    tconv_kernel<<<dim3(32, 4, 32), tb>>>(m_in, 128, 1024, 1.0f, 0);
    tconv_kernel<<<dim3(32, 4, 8),  tb>>>(q_in, 128, 1024, SCALE_, 1);

    // 2. GEMM1: scores -> p region of d_out
    gemm_fp16<<<dim3(8, 8, 32), 128, GSMEM>>>(
        p, 128, 1024,
        (unsigned long long)1024 * 128, (unsigned long long)1024 * 128,
        (unsigned long long)HW_ * HW_, 2, 0);

    // 3. fused softmax (in place) + pT convert/transpose
    dim3 gs(HW_ / 32, B_);
    softmax_pt_kernel<<<gs, 256>>>(p);

    // 4. GEMM2: mem -> mem_out channels [0:512]
    gemm_fp16<<<dim3(4, 8, 8), 128, GSMEM>>>(
        mem_out, 4096, 1024,
        (unsigned long long)512 * 4096, (unsigned long long)1024 * 4096,
        (unsigned long long)1024 * 1024, 0, 1);

    // 5. concat q_out
    copy_qout_kernel<<<(B_ * Do_ * HW_ / 4 + 255) / 256, 256>>>(
        (const float4*)q_out, (float4*)mem_out);
}